// round 3
// baseline (speedup 1.0000x reference)
#include <cuda_runtime.h>
#include <cuda_bf16.h>
#include <math.h>

// Fixed problem constants (IGMC dataset)
#define NMAX 100000
#define EMAX 1600000
#define RR   5
#define DD   32
#define NBB  2
#define FF   4
#define CC   5
#define BMAX 512

// ---------------- scratch (device globals; no allocation) ----------------
__device__ float g_h0[NMAX * DD];                       // 12.8 MB
__device__ float g_h1[NMAX * DD];                       // 12.8 MB
__device__ float g_xr[(size_t)RR * NMAX * DD];          // 64 MB (L2-resident working set)
__device__ int   g_cntNR[NMAX * RR];                    // per-(dst,rel) counts
__device__ int   g_rowptr[NMAX + 1];
__device__ int   g_cursor[NMAX];
__device__ int   g_blocksums[256];
__device__ int   g_blockoff[256];
__device__ unsigned long long g_recs[EMAX];             // packed {off, w} per edge, dst-sorted
__device__ float g_W[RR * DD * DD];                     // combined relation weights (current layer)
__device__ float g_concat[BMAX * 4 * DD];               // start-node states, all 4 layers

__device__ __forceinline__ const float* hbuf_in(int sel, const float* ext) {
    return (sel == 1) ? g_h0 : ((sel == 2) ? g_h1 : ext);
}
__device__ __forceinline__ float* hbuf_out(int sel) {
    return (sel == 1) ? g_h0 : g_h1;
}

// ---------------- CSR build ----------------
__global__ void k_zero_cnt(int n) {
    int i = blockIdx.x * blockDim.x + threadIdx.x;
    if (i < n) g_cntNR[i] = 0;
}

__global__ void k_count(const int* __restrict__ ei, const int* __restrict__ et, int E) {
    int e = blockIdx.x * blockDim.x + threadIdx.x;
    if (e >= E) return;
    int d = ei[E + e];
    int t = et[e];
    atomicAdd(&g_cntNR[d * RR + t], 1);
}

// block-level inclusive scan of per-node degree (derived from cntNR)
__global__ void k_scanA(int N) {
    __shared__ int s[1024];
    int t = threadIdx.x;
    int i = blockIdx.x * 1024 + t;
    int v = 0;
    if (i < N) {
        int base = i * RR;
#pragma unroll
        for (int r = 0; r < RR; r++) v += g_cntNR[base + r];
    }
    s[t] = v;
    __syncthreads();
    for (int st = 1; st < 1024; st <<= 1) {
        int x = (t >= st) ? s[t - st] : 0;
        __syncthreads();
        s[t] += x;
        __syncthreads();
    }
    if (i < N) g_rowptr[i] = s[t];               // inclusive, fixed up in scanC
    if (t == 1023) g_blocksums[blockIdx.x] = s[1023];
}

__global__ void k_scanB(int nblk) {
    if (threadIdx.x == 0 && blockIdx.x == 0) {
        int run = 0;
        for (int b = 0; b < nblk; b++) {
            int v = g_blocksums[b];
            g_blockoff[b] = run;
            run += v;
        }
    }
}

__global__ void k_scanC(int N, int E) {
    int t = threadIdx.x;
    int i = blockIdx.x * 1024 + t;
    if (i < N) {
        int base = i * RR;
        int deg = 0;
#pragma unroll
        for (int r = 0; r < RR; r++) deg += g_cntNR[base + r];
        int excl = g_rowptr[i] - deg + g_blockoff[blockIdx.x];
        g_rowptr[i] = excl;
        g_cursor[i] = excl;
    }
    if (i == 0) g_rowptr[N] = E;
}

__global__ void k_fill(const int* __restrict__ ei, const int* __restrict__ et, int E, int N) {
    int e = blockIdx.x * blockDim.x + threadIdx.x;
    if (e >= E) return;
    int s = ei[e];
    int d = ei[E + e];
    int t = et[e];
    int p = atomicAdd(&g_cursor[d], 1);
    int c = g_cntNR[d * RR + t];                 // >= 1 (this edge was counted)
    float w = 1.0f / (float)c;
    unsigned long long rec =
        (unsigned long long)(unsigned)(t * N + s) |
        ((unsigned long long)__float_as_uint(w) << 32);
    g_recs[p] = rec;
}

// ---------------- per-layer kernels ----------------
// W[r][i][d] = sum_b comp[r,b] * basis[b,i,d]
__global__ void k_combineW(const float* __restrict__ basis, const float* __restrict__ comp, int I) {
    int idx = blockIdx.x * blockDim.x + threadIdx.x;
    int tot = RR * I * DD;
    if (idx >= tot) return;
    int r = idx / (I * DD);
    int rem = idx - r * (I * DD);
    float s = 0.f;
#pragma unroll
    for (int b = 0; b < NBB; b++) s += comp[r * NBB + b] * basis[b * I * DD + rem];
    g_W[idx] = s;
}

// xr[r][n][:] = h[n][:] @ W[r]  (warp per node, lane = output dim)
template <int I>
__global__ void k_xr(const float* __restrict__ hext, int inSel, int N) {
    __shared__ float Wsm[RR * I * DD];
    const float* __restrict__ h = hbuf_in(inSel, hext);
    int tid = threadIdx.x;
    for (int idx = tid; idx < RR * I * DD; idx += blockDim.x) Wsm[idx] = g_W[idx];
    __syncthreads();
    int warp = tid >> 5, lane = tid & 31;
    int n = blockIdx.x * 8 + warp;
    if (n >= N) return;
    float hv = (lane < I) ? h[n * I + lane] : 0.f;
    float acc[RR];
#pragma unroll
    for (int r = 0; r < RR; r++) acc[r] = 0.f;
#pragma unroll
    for (int i = 0; i < I; i++) {
        float hi = __shfl_sync(0xffffffffu, hv, i);
#pragma unroll
        for (int r = 0; r < RR; r++) acc[r] += hi * Wsm[(r * I + i) * DD + lane];
    }
#pragma unroll
    for (int r = 0; r < RR; r++) g_xr[((size_t)r * N + n) * DD + lane] = acc[r];
}

// out[n][:] = tanh( bias + h[n] @ root + sum_{e in-edges(n)} w_e * xr[off_e][:] )
template <int I>
__global__ void k_agg(const float* __restrict__ hext, int inSel,
                      const float* __restrict__ root, const float* __restrict__ bias,
                      int outSel, int N) {
    const float* __restrict__ h = hbuf_in(inSel, hext);
    float* __restrict__ out = hbuf_out(outSel);
    int tid = threadIdx.x;
    int warp = tid >> 5, lane = tid & 31;
    int n = blockIdx.x * 8 + warp;
    if (n >= N) return;

    float acc = bias[lane];
    float hv = (lane < I) ? h[n * I + lane] : 0.f;
#pragma unroll
    for (int i = 0; i < I; i++) {
        float hi = __shfl_sync(0xffffffffu, hv, i);
        acc += hi * root[i * DD + lane];
    }

    int beg = g_rowptr[n];
    int end = g_rowptr[n + 1];
    for (int base = beg; base < end; base += 32) {
        int k = base + lane;
        unsigned long long rec = (k < end) ? g_recs[k] : 0ull;
        int cnt = min(32, end - base);
        int j = 0;
        while (j < cnt) {
#pragma unroll
            for (int u = 0; u < 8; u++) {
                int jj = j + u;
                if (jj < cnt) {
                    unsigned long long rj = __shfl_sync(0xffffffffu, rec, jj);
                    int off = (int)(rj & 0xffffffffu);
                    float w = __uint_as_float((unsigned)(rj >> 32));
                    acc += w * g_xr[(size_t)off * DD + lane];
                }
            }
            j += 8;
        }
    }
    out[n * DD + lane] = tanhf(acc);
}

__global__ void k_gather(int hSel, const int* __restrict__ start, int layer) {
    const float* __restrict__ h = (hSel == 1) ? g_h0 : g_h1;
    int b = blockIdx.x;
    int lane = threadIdx.x;
    int node = start[b];
    g_concat[b * (4 * DD) + layer * DD + lane] = h[node * DD + lane];
}

__global__ void k_mlp(const float* __restrict__ w1, const float* __restrict__ b1,
                      const float* __restrict__ w2, const float* __restrict__ b2,
                      float* __restrict__ out) {
    __shared__ float cs[128];
    __shared__ float h1[128];
    __shared__ float lg[CC];
    int b = blockIdx.x;
    int t = threadIdx.x;
    cs[t] = g_concat[b * 128 + t];
    __syncthreads();
    float s = b1[t];
#pragma unroll 8
    for (int k = 0; k < 128; k++) s += cs[k] * w1[k * 128 + t];
    h1[t] = fmaxf(s, 0.f);
    __syncthreads();
    if (t < CC) {
        float s2 = b2[t];
#pragma unroll 8
        for (int k = 0; k < 128; k++) s2 += h1[k] * w2[k * CC + t];
        lg[t] = s2;
    }
    __syncthreads();
    if (t < CC) {
        float m = lg[0];
#pragma unroll
        for (int c = 1; c < CC; c++) m = fmaxf(m, lg[c]);
        float sum = 0.f;
#pragma unroll
        for (int c = 0; c < CC; c++) sum += expf(lg[c] - m);
        out[b * CC + t] = lg[t] - m - logf(sum);
    }
}

// ---------------- launch ----------------
extern "C" void kernel_launch(void* const* d_in, const int* in_sizes, int n_in,
                              void* d_out, int out_size) {
    const float* x      = (const float*)d_in[0];
    const int*   ei     = (const int*)d_in[1];
    const int*   et     = (const int*)d_in[2];
    const int*   start  = (const int*)d_in[3];
    const float* basis0 = (const float*)d_in[4];
    const float* comp0  = (const float*)d_in[5];
    const float* root0  = (const float*)d_in[6];
    const float* bias0  = (const float*)d_in[7];
    const float* basis  = (const float*)d_in[8];
    const float* comp   = (const float*)d_in[9];
    const float* root   = (const float*)d_in[10];
    const float* bias   = (const float*)d_in[11];
    const float* l1w    = (const float*)d_in[12];
    const float* l1b    = (const float*)d_in[13];
    const float* l2w    = (const float*)d_in[14];
    const float* l2b    = (const float*)d_in[15];
    float* out = (float*)d_out;

    int N = in_sizes[0] / FF;
    int E = in_sizes[2];
    int B = in_sizes[3];

    // ---- build dst-sorted CSR with precomputed per-edge norm weight ----
    k_zero_cnt<<<(N * RR + 255) / 256, 256>>>(N * RR);
    k_count<<<(E + 255) / 256, 256>>>(ei, et, E);
    int nblk = (N + 1023) / 1024;
    k_scanA<<<nblk, 1024>>>(N);
    k_scanB<<<1, 32>>>(nblk);
    k_scanC<<<nblk, 1024>>>(N, E);
    k_fill<<<(E + 255) / 256, 256>>>(ei, et, E, N);

    int nodeBlocks = (N + 7) / 8;

    // ---- layer 0 (in = x, F=4) ----
    k_combineW<<<(RR * FF * DD + 255) / 256, 256>>>(basis0, comp0, FF);
    k_xr<FF><<<nodeBlocks, 256>>>(x, 0, N);
    k_agg<FF><<<nodeBlocks, 256>>>(x, 0, root0, bias0, /*outSel=*/1, N);
    k_gather<<<B, 32>>>(1, start, 0);

    // ---- layers 1..3 (in = out = 32) ----
    int inSel = 1;
    for (int l = 0; l < 3; l++) {
        int outSel = (inSel == 1) ? 2 : 1;
        k_combineW<<<(RR * DD * DD + 255) / 256, 256>>>(
            basis + (size_t)l * NBB * DD * DD, comp + (size_t)l * RR * NBB, DD);
        k_xr<DD><<<nodeBlocks, 256>>>(nullptr, inSel, N);
        k_agg<DD><<<nodeBlocks, 256>>>(nullptr, inSel,
                                       root + (size_t)l * DD * DD, bias + (size_t)l * DD,
                                       outSel, N);
        k_gather<<<B, 32>>>(outSel, start, l + 1);
        inSel = outSel;
    }

    // ---- readout MLP + log_softmax ----
    k_mlp<<<B, 128>>>(l1w, l1b, l2w, l2b, out);
}

// round 4
// speedup vs baseline: 2.1141x; 2.1141x over previous
#include <cuda_runtime.h>
#include <cuda_bf16.h>
#include <math.h>

// Fixed problem constants (IGMC dataset)
#define NMAX 100000
#define EMAX 1600000
#define RR   5
#define DD   32
#define NBB  2
#define FF   4
#define CC   5
#define BMAX 512

// ---------------- scratch (device globals; no allocation) ----------------
__device__ float g_h0[NMAX * DD];                       // 12.8 MB
__device__ float g_h1[NMAX * DD];                       // 12.8 MB
__device__ float g_agg[NMAX * 2 * DD];                  // basis-space accumulators, 25.6 MB max
__device__ int   g_cntNR[NMAX * RR];
__device__ int   g_rowptr[NMAX + 1];
__device__ int   g_cursor[NMAX];
__device__ int   g_blocksums[256];
__device__ int   g_blockoff[256];
__device__ unsigned long long g_recs[EMAX];             // packed {w, src<<3|rel}, dst-sorted
__device__ float g_W[96 * DD];                          // combined [root; basis0; basis1] cols
__device__ float g_concat[BMAX * 4 * DD];

__device__ __forceinline__ const float* hbuf_in(int sel, const float* ext) {
    return (sel == 1) ? g_h0 : ((sel == 2) ? g_h1 : ext);
}
__device__ __forceinline__ float* hbuf_out(int sel) {
    return (sel == 1) ? g_h0 : g_h1;
}

// ---------------- CSR build ----------------
__global__ void k_zero_cnt(int n) {
    int i = blockIdx.x * blockDim.x + threadIdx.x;
    if (i < n) g_cntNR[i] = 0;
}

__global__ void k_count(const int* __restrict__ ei, const int* __restrict__ et, int E) {
    int e = blockIdx.x * blockDim.x + threadIdx.x;
    if (e >= E) return;
    int d = ei[E + e];
    int t = et[e];
    atomicAdd(&g_cntNR[d * RR + t], 1);
}

__global__ void k_scanA(int N) {
    __shared__ int s[1024];
    int t = threadIdx.x;
    int i = blockIdx.x * 1024 + t;
    int v = 0;
    if (i < N) {
        int base = i * RR;
#pragma unroll
        for (int r = 0; r < RR; r++) v += g_cntNR[base + r];
    }
    s[t] = v;
    __syncthreads();
    for (int st = 1; st < 1024; st <<= 1) {
        int x = (t >= st) ? s[t - st] : 0;
        __syncthreads();
        s[t] += x;
        __syncthreads();
    }
    if (i < N) g_rowptr[i] = s[t];               // inclusive within block
    if (t == 1023) g_blocksums[blockIdx.x] = s[1023];
}

__global__ void k_scanB(int nblk) {
    // small parallel exclusive scan over <=256 block sums
    __shared__ int s[256];
    int t = threadIdx.x;
    s[t] = (t < nblk) ? g_blocksums[t] : 0;
    __syncthreads();
    for (int st = 1; st < 256; st <<= 1) {
        int x = (t >= st) ? s[t - st] : 0;
        __syncthreads();
        s[t] += x;
        __syncthreads();
    }
    if (t < nblk) g_blockoff[t] = s[t] - g_blocksums[t];
}

__global__ void k_scanC(int N, int E) {
    int t = threadIdx.x;
    int i = blockIdx.x * 1024 + t;
    if (i < N) {
        int base = i * RR;
        int deg = 0;
#pragma unroll
        for (int r = 0; r < RR; r++) deg += g_cntNR[base + r];
        int excl = g_rowptr[i] - deg + g_blockoff[blockIdx.x];
        g_rowptr[i] = excl;
        g_cursor[i] = excl;
    }
    if (i == 0) g_rowptr[N] = E;
}

__global__ void k_fill(const int* __restrict__ ei, const int* __restrict__ et, int E) {
    int e = blockIdx.x * blockDim.x + threadIdx.x;
    if (e >= E) return;
    int s = ei[e];
    int d = ei[E + e];
    int t = et[e];
    int p = atomicAdd(&g_cursor[d], 1);
    int c = g_cntNR[d * RR + t];                 // >= 1
    float w = 1.0f / (float)c;
    unsigned long long rec =
        (unsigned long long)(unsigned)((s << 3) | t) |
        ((unsigned long long)__float_as_uint(w) << 32);
    g_recs[p] = rec;
}

// ---------------- per-layer kernels ----------------
// Build combined weight matrix g_W[k][d], k in [0, 3I): [root (I rows); basis_0 (I); basis_1 (I)]
__global__ void k_buildW(const float* __restrict__ root, const float* __restrict__ basis, int I) {
    int idx = blockIdx.x * blockDim.x + threadIdx.x;
    int K = 3 * I;
    if (idx >= K * DD) return;
    int k = idx >> 5, d = idx & 31;
    float v;
    if (k < I) v = root[k * DD + d];
    else {
        int kk = k - I;
        int b = (kk >= I) ? 1 : 0;
        int i = kk - b * I;
        v = basis[(b * I + i) * DD + d];
    }
    g_W[idx] = v;
}

// Edge aggregation in basis space:
//   accB_b[n][i] = sum_{e: dst=n} w_e * comp[r_e, b] * h[src_e][i]
template <int I>
__global__ void k_edge(const float* __restrict__ hext, int inSel,
                       const float* __restrict__ comp, int N) {
    __shared__ float c0s[8], c1s[8];
    if (threadIdx.x < 8) {
        int r = threadIdx.x;
        c0s[r] = (r < RR) ? comp[r * NBB + 0] : 0.f;
        c1s[r] = (r < RR) ? comp[r * NBB + 1] : 0.f;
    }
    __syncthreads();
    const float* __restrict__ h = hbuf_in(inSel, hext);
    int warp = threadIdx.x >> 5, lane = threadIdx.x & 31;
    int n = blockIdx.x * 8 + warp;
    if (n >= N) return;

    float a0 = 0.f, a1 = 0.f;
    int beg = g_rowptr[n];
    int end = g_rowptr[n + 1];
    for (int base = beg; base < end; base += 32) {
        int k = base + lane;
        unsigned long long rec = (k < end) ? g_recs[k] : 0ull;
        int cnt = min(32, end - base);
        int j = 0;
        while (j < cnt) {
#pragma unroll
            for (int u = 0; u < 8; u++) {
                int jj = j + u;
                if (jj < cnt) {
                    unsigned long long rj = __shfl_sync(0xffffffffu, rec, jj);
                    unsigned lo = (unsigned)rj;
                    float w = __uint_as_float((unsigned)(rj >> 32));
                    int rel = lo & 7;
                    int src = (int)(lo >> 3);
                    float v;
                    if (I == DD) v = h[src * DD + lane];
                    else v = (lane < I) ? h[src * I + lane] : 0.f;
                    a0 += (w * c0s[rel]) * v;
                    a1 += (w * c1s[rel]) * v;
                }
            }
            j += 8;
        }
    }
    if (I == DD) {
        g_agg[n * 64 + lane] = a0;
        g_agg[n * 64 + 32 + lane] = a1;
    } else if (lane < I) {
        g_agg[n * (2 * I) + lane] = a0;
        g_agg[n * (2 * I) + I + lane] = a1;
    }
}

// Fused transform: out[n][:] = tanh( bias + [h[n] | accB0[n] | accB1[n]] @ g_W )
// Weight column per lane lives in registers; input row broadcast via shfl.
template <int I>
__global__ void __launch_bounds__(256) k_trans(const float* __restrict__ hext, int inSel,
                                               const float* __restrict__ bias,
                                               int outSel, int N) {
    constexpr int K = 3 * I;
    const float* __restrict__ h = hbuf_in(inSel, hext);
    float* __restrict__ out = hbuf_out(outSel);
    int lane = threadIdx.x & 31;
    float w[K];
#pragma unroll
    for (int k = 0; k < K; k++) w[k] = g_W[k * DD + lane];
    float bv = bias[lane];

    int warpG = (blockIdx.x * blockDim.x + threadIdx.x) >> 5;
    int nwarps = (gridDim.x * blockDim.x) >> 5;
    for (int n = warpG; n < N; n += nwarps) {
        float acc = bv;
        if (I == DD) {
            float i0 = h[n * DD + lane];
            float i1 = g_agg[n * 64 + lane];
            float i2 = g_agg[n * 64 + 32 + lane];
#pragma unroll
            for (int k = 0; k < 32; k++) acc += __shfl_sync(0xffffffffu, i0, k) * w[k];
#pragma unroll
            for (int k = 0; k < 32; k++) acc += __shfl_sync(0xffffffffu, i1, k) * w[32 + k];
#pragma unroll
            for (int k = 0; k < 32; k++) acc += __shfl_sync(0xffffffffu, i2, k) * w[64 + k];
        } else {
            float i0 = 0.f;
            if (lane < I) i0 = h[n * I + lane];
            else if (lane < K) i0 = g_agg[n * (2 * I) + (lane - I)];
#pragma unroll
            for (int k = 0; k < K; k++) acc += __shfl_sync(0xffffffffu, i0, k) * w[k];
        }
        out[n * DD + lane] = tanhf(acc);
    }
}

__global__ void k_gather(int hSel, const int* __restrict__ start, int layer) {
    const float* __restrict__ h = (hSel == 1) ? g_h0 : g_h1;
    int b = blockIdx.x;
    int lane = threadIdx.x;
    int node = start[b];
    g_concat[b * (4 * DD) + layer * DD + lane] = h[node * DD + lane];
}

__global__ void k_mlp(const float* __restrict__ w1, const float* __restrict__ b1,
                      const float* __restrict__ w2, const float* __restrict__ b2,
                      float* __restrict__ out) {
    __shared__ float cs[128];
    __shared__ float h1[128];
    __shared__ float lg[CC];
    int b = blockIdx.x;
    int t = threadIdx.x;
    cs[t] = g_concat[b * 128 + t];
    __syncthreads();
    float s = b1[t];
#pragma unroll 8
    for (int k = 0; k < 128; k++) s += cs[k] * w1[k * 128 + t];
    h1[t] = fmaxf(s, 0.f);
    __syncthreads();
    if (t < CC) {
        float s2 = b2[t];
#pragma unroll 8
        for (int k = 0; k < 128; k++) s2 += h1[k] * w2[k * CC + t];
        lg[t] = s2;
    }
    __syncthreads();
    if (t < CC) {
        float m = lg[0];
#pragma unroll
        for (int c = 1; c < CC; c++) m = fmaxf(m, lg[c]);
        float sum = 0.f;
#pragma unroll
        for (int c = 0; c < CC; c++) sum += expf(lg[c] - m);
        out[b * CC + t] = lg[t] - m - logf(sum);
    }
}

// ---------------- launch ----------------
extern "C" void kernel_launch(void* const* d_in, const int* in_sizes, int n_in,
                              void* d_out, int out_size) {
    const float* x      = (const float*)d_in[0];
    const int*   ei     = (const int*)d_in[1];
    const int*   et     = (const int*)d_in[2];
    const int*   start  = (const int*)d_in[3];
    const float* basis0 = (const float*)d_in[4];
    const float* comp0  = (const float*)d_in[5];
    const float* root0  = (const float*)d_in[6];
    const float* bias0  = (const float*)d_in[7];
    const float* basis  = (const float*)d_in[8];
    const float* comp   = (const float*)d_in[9];
    const float* root   = (const float*)d_in[10];
    const float* bias   = (const float*)d_in[11];
    const float* l1w    = (const float*)d_in[12];
    const float* l1b    = (const float*)d_in[13];
    const float* l2w    = (const float*)d_in[14];
    const float* l2b    = (const float*)d_in[15];
    float* out = (float*)d_out;

    int N = in_sizes[0] / FF;
    int E = in_sizes[2];
    int B = in_sizes[3];

    // ---- build dst-sorted CSR with per-edge norm weight + relation ----
    k_zero_cnt<<<(N * RR + 255) / 256, 256>>>(N * RR);
    k_count<<<(E + 255) / 256, 256>>>(ei, et, E);
    int nblk = (N + 1023) / 1024;
    k_scanA<<<nblk, 1024>>>(N);
    k_scanB<<<1, 256>>>(nblk);
    k_scanC<<<nblk, 1024>>>(N, E);
    k_fill<<<(E + 255) / 256, 256>>>(ei, et, E);

    int nodeBlocks = (N + 7) / 8;
    const int transGrid = 512;

    // ---- layer 0 (in = x, F=4) ----
    k_buildW<<<(3 * FF * DD + 255) / 256, 256>>>(root0, basis0, FF);
    k_edge<FF><<<nodeBlocks, 256>>>(x, 0, comp0, N);
    k_trans<FF><<<transGrid, 256>>>(x, 0, bias0, /*outSel=*/1, N);
    k_gather<<<B, 32>>>(1, start, 0);

    // ---- layers 1..3 (in = out = 32) ----
    int inSel = 1;
    for (int l = 0; l < 3; l++) {
        int outSel = (inSel == 1) ? 2 : 1;
        k_buildW<<<(3 * DD * DD + 255) / 256, 256>>>(
            root + (size_t)l * DD * DD, basis + (size_t)l * NBB * DD * DD, DD);
        k_edge<DD><<<nodeBlocks, 256>>>(nullptr, inSel, comp + (size_t)l * RR * NBB, N);
        k_trans<DD><<<transGrid, 256>>>(nullptr, inSel, bias + (size_t)l * DD, outSel, N);
        k_gather<<<B, 32>>>(outSel, start, l + 1);
        inSel = outSel;
    }

    // ---- readout MLP + log_softmax ----
    k_mlp<<<B, 128>>>(l1w, l1b, l2w, l2b, out);
}